// round 3
// baseline (speedup 1.0000x reference)
#include <cuda_runtime.h>
#include <math.h>

#define EPS 1e-8f
#define TARGET_RADIUS 0.99f
#define Bsz 32
#define Dsz 1024
#define BD (Bsz * Dsz)
#define NBLK 128   // recurrence grid size (single wave)

// ---------------- device scratch ----------------
__device__ float g_Wx[2048L * Bsz * Dsz];   // precomputed x @ W_x^T  (268 MB)
__device__ float g_scale;                   // spectral scaling of W_h
__device__ unsigned int g_arrive;
__device__ unsigned int g_release;

// ---------------- reset + h0 copy ----------------
__global__ void reset_copy_kernel(const float* __restrict__ h0, float* __restrict__ hglob) {
    int i = blockIdx.x * blockDim.x + threadIdx.x;
    if (i == 0) { g_arrive = 0u; g_release = 0u; }
    if (i < BD) hglob[i] = h0[i];
}

// ---------------- block reduction helper ----------------
__device__ __forceinline__ float block_reduce_sum(float v, float* red) {
    int lane = threadIdx.x & 31, w = threadIdx.x >> 5;
    #pragma unroll
    for (int o = 16; o; o >>= 1) v += __shfl_xor_sync(0xffffffffu, v, o);
    if (lane == 0) red[w] = v;
    __syncthreads();
    if (w == 0) {
        float r = (lane < (int)(blockDim.x >> 5)) ? red[lane] : 0.0f;
        #pragma unroll
        for (int o = 16; o; o >>= 1) r += __shfl_xor_sync(0xffffffffu, r, o);
        if (lane == 0) red[0] = r;
    }
    __syncthreads();
    float out = red[0];
    __syncthreads();
    return out;
}

// ---------------- spectral norm (1 CTA, 1024 threads) ----------------
__global__ __launch_bounds__(1024) void spectral_kernel(
    const float* __restrict__ W, const float* __restrict__ u0) {
    __shared__ float u_sh[Dsz];
    __shared__ float v_sh[Dsz];
    __shared__ float red[32];
    int i = threadIdx.x;

    float u0v = u0[i];
    float n0 = sqrtf(block_reduce_sum(u0v * u0v, red));
    u_sh[i] = u0v / n0;     // reference: no eps on the initial normalize
    __syncthreads();

    float sigma = 0.0f;
    for (int it = 0; it < 3; it++) {
        // v = W^T u  (column access, coalesced across threads)
        float acc = 0.0f;
        #pragma unroll 8
        for (int k = 0; k < Dsz; k++) acc += W[k * Dsz + i] * u_sh[k];
        float nv = sqrtf(block_reduce_sum(acc * acc, red));
        v_sh[i] = acc / (nv + EPS);
        __syncthreads();
        // u_raw = W v  (row access per thread)
        float acc2 = 0.0f;
        #pragma unroll 8
        for (int c = 0; c < Dsz; c++) acc2 += W[i * Dsz + c] * v_sh[c];
        float ss = block_reduce_sum(acc2 * acc2, red);
        float nu = sqrtf(ss);
        u_sh[i] = acc2 / (nu + EPS);
        __syncthreads();
        // sigma = u . (W v) = ss / (nu + eps), with u from THIS iter, v from THIS iter
        sigma = ss / (nu + EPS);
    }
    if (i == 0) g_scale = TARGET_RADIUS / (sigma + EPS);
}

// ---------------- Wx GEMM:  C[M][1024] = A[M][1024] * B[1024][1024]^T ----------------
__global__ __launch_bounds__(256) void gemm_xwx_kernel(
    const float* __restrict__ A, const float* __restrict__ B, int M) {
    __shared__ float As[16][132];
    __shared__ float Bs[16][132];
    int tid = threadIdx.x;
    int m0 = blockIdx.y * 128, n0 = blockIdx.x * 128;
    int tx = tid & 15, ty = tid >> 4;
    int lr = tid >> 2;            // 0..63
    int lc = (tid & 3) << 2;      // 0,4,8,12

    float acc[8][8];
    #pragma unroll
    for (int i = 0; i < 8; i++)
        #pragma unroll
        for (int j = 0; j < 8; j++) acc[i][j] = 0.0f;

    const float* Aptr = A + (size_t)(m0 + lr) * Dsz + lc;
    const float* Bptr = B + (size_t)(n0 + lr) * Dsz + lc;

    for (int k0 = 0; k0 < Dsz; k0 += 16) {
        float4 a0 = *(const float4*)(Aptr);
        float4 a1 = *(const float4*)(Aptr + 64 * Dsz);
        float4 b0 = *(const float4*)(Bptr);
        float4 b1 = *(const float4*)(Bptr + 64 * Dsz);
        Aptr += 16; Bptr += 16;
        __syncthreads();
        As[lc + 0][lr] = a0.x; As[lc + 1][lr] = a0.y; As[lc + 2][lr] = a0.z; As[lc + 3][lr] = a0.w;
        As[lc + 0][lr + 64] = a1.x; As[lc + 1][lr + 64] = a1.y; As[lc + 2][lr + 64] = a1.z; As[lc + 3][lr + 64] = a1.w;
        Bs[lc + 0][lr] = b0.x; Bs[lc + 1][lr] = b0.y; Bs[lc + 2][lr] = b0.z; Bs[lc + 3][lr] = b0.w;
        Bs[lc + 0][lr + 64] = b1.x; Bs[lc + 1][lr + 64] = b1.y; Bs[lc + 2][lr + 64] = b1.z; Bs[lc + 3][lr + 64] = b1.w;
        __syncthreads();
        #pragma unroll
        for (int kk = 0; kk < 16; kk++) {
            float a[8], b[8];
            *(float4*)(a)     = *(const float4*)&As[kk][ty * 4];
            *(float4*)(a + 4) = *(const float4*)&As[kk][64 + ty * 4];
            *(float4*)(b)     = *(const float4*)&Bs[kk][tx * 4];
            *(float4*)(b + 4) = *(const float4*)&Bs[kk][64 + tx * 4];
            #pragma unroll
            for (int i = 0; i < 8; i++)
                #pragma unroll
                for (int j = 0; j < 8; j++) acc[i][j] += a[i] * b[j];
        }
    }
    #pragma unroll
    for (int i = 0; i < 8; i++) {
        int m = m0 + ((i < 4) ? (ty * 4 + i) : (64 + ty * 4 + (i - 4)));
        float4 v0 = make_float4(acc[i][0], acc[i][1], acc[i][2], acc[i][3]);
        float4 v1 = make_float4(acc[i][4], acc[i][5], acc[i][6], acc[i][7]);
        *(float4*)&g_Wx[(size_t)m * Dsz + n0 + tx * 4]      = v0;
        *(float4*)&g_Wx[(size_t)m * Dsz + n0 + 64 + tx * 4] = v1;
    }
}

// ---------------- persistent recurrence kernel (128 CTAs, grid barrier) ----------------
__global__ __launch_bounds__(256, 1) void recur_kernel(
    const float* __restrict__ Wh, const float* __restrict__ bvec,
    const float* __restrict__ bgate, float* __restrict__ outp,
    float* __restrict__ hglob, int T) {
    __shared__ float4 sh_h[8 * 256];   // 8 b-rows x 256 quads, XOR-swizzled, 32 KB
    const int tid = threadIdx.x;
    const int warp = tid >> 5, lane = tid & 31;
    const int ib = blockIdx.x & 3;        // b group (4)
    const int id = blockIdx.x >> 2;       // d group (32)
    const int d_base = id * 32 + warp * 4;
    const int b_base = ib * 8;

    // W_h_n rows in registers: warp owns 4 d-rows; lane owns k in [32*lane, 32*lane+32)
    float scale = g_scale;
    float wreg[4][32];
    #pragma unroll
    for (int r = 0; r < 4; r++) {
        const float* wrow = Wh + (size_t)(d_base + r) * Dsz + lane * 32;
        #pragma unroll
        for (int j = 0; j < 32; j++) wreg[r][j] = wrow[j] * scale;
    }

    // final (d,b) mapping: butterfly leaves lane L with sum of acc[bitrev5(L)]
    int idx = ((lane & 1) << 4) | ((lane & 2) << 2) | (lane & 4) | ((lane & 8) >> 2) | ((lane & 16) >> 4);
    int d_out = d_base + (idx >> 3);
    int b_out = b_base + (idx & 7);
    size_t off = (size_t)b_out * Dsz + d_out;
    float bias_b = bvec[d_out];
    float bias_g = bgate[d_out];

    for (int t = 0; t < T; t++) {
        // prefetch Wx (no dependency on barrier)
        float wx = __ldg(&g_Wx[(size_t)t * BD + off]);

        if (t > 0) {
            if (tid == 0) {
                while (*((volatile unsigned int*)&g_release) < (unsigned int)t) { }
            }
            __syncthreads();
        }

        // stage h[t] slice into SMEM with swizzle; __ldcg to avoid stale L1
        const float4* hsrc = (const float4*)(hglob + (size_t)t * BD + (size_t)b_base * Dsz);
        #pragma unroll
        for (int i2 = 0; i2 < 8; i2++) {
            int f = tid + 256 * i2;            // quad index over 8 rows x 256 quads
            int b = f >> 8, q = f & 255;
            float4 v = __ldcg(&hsrc[f]);
            sh_h[(b << 8) + (q ^ ((q >> 3) & 7))] = v;
        }
        __syncthreads();

        float acc[32];
        #pragma unroll
        for (int a = 0; a < 32; a++) acc[a] = 0.0f;

        #pragma unroll
        for (int j8 = 0; j8 < 8; j8++) {
            float4 hq[8];
            #pragma unroll
            for (int b = 0; b < 8; b++) {
                int q = lane * 8 + j8;
                hq[b] = sh_h[(b << 8) + (q ^ (lane & 7))];
            }
            #pragma unroll
            for (int r = 0; r < 4; r++)
                #pragma unroll
                for (int b = 0; b < 8; b++) {
                    acc[r * 8 + b] += wreg[r][j8 * 4 + 0] * hq[b].x;
                    acc[r * 8 + b] += wreg[r][j8 * 4 + 1] * hq[b].y;
                    acc[r * 8 + b] += wreg[r][j8 * 4 + 2] * hq[b].z;
                    acc[r * 8 + b] += wreg[r][j8 * 4 + 3] * hq[b].w;
                }
        }

        // multi-value butterfly: 32 accs -> 1 warp-sum per lane (31 shfl)
        #pragma unroll
        for (int s = 0; s < 5; s++) {
            int bit = 1 << s, n = 16 >> s;
            #pragma unroll
            for (int j = 0; j < n; j++) {
                float send = (lane & bit) ? acc[j] : acc[j + n];
                float recv = __shfl_xor_sync(0xffffffffu, send, bit);
                acc[j] = ((lane & bit) ? acc[j + n] : acc[j]) + recv;
            }
        }

        float raw = acc[0] + wx + bias_b;
        float h_new = tanhf(raw);
        float g = wx + h_new + bias_g;
        float outv = h_new * (g / (1.0f + __expf(-g)));

        hglob[(size_t)(t + 1) * BD + off] = h_new;
        outp[(size_t)t * BD + off] = outv;

        // grid barrier arrive
        __threadfence();
        __syncthreads();
        if (tid == 0) {
            unsigned int a = atomicAdd(&g_arrive, 1u) + 1u;
            if (a == (unsigned int)NBLK * (unsigned int)(t + 1)) {
                atomicExch(&g_release, (unsigned int)(t + 1));
            }
        }
    }
}

// ---------------- launch ----------------
extern "C" void kernel_launch(void* const* d_in, const int* in_sizes, int n_in,
                              void* d_out, int out_size) {
    const float* x   = (const float*)d_in[0];
    // d_in[1] = z (unused by reference in this gate mode)
    const float* h0  = (const float*)d_in[2];
    const float* W_x = (const float*)d_in[3];
    const float* W_h = (const float*)d_in[4];
    const float* bv  = (const float*)d_in[5];
    const float* bg  = (const float*)d_in[6];
    const float* u0  = (const float*)d_in[7];

    int T = in_sizes[0] / BD;
    float* outp  = (float*)d_out;                 // [T, B, D]
    float* hglob = outp + (size_t)T * BD;         // [T+1, B, D]

    reset_copy_kernel<<<32, 1024>>>(h0, hglob);
    spectral_kernel<<<1, 1024>>>(W_h, u0);
    dim3 grid_g(Dsz / 128, (T * Bsz) / 128);
    gemm_xwx_kernel<<<grid_g, 256>>>(x, W_x, T * Bsz);
    recur_kernel<<<NBLK, 256>>>(W_h, bv, bg, outp, hglob, T);
}

// round 4
// speedup vs baseline: 1.4766x; 1.4766x over previous
#include <cuda_runtime.h>
#include <math.h>

#define EPS 1e-8f
#define TARGET_RADIUS 0.99f
#define Bsz 32
#define Dsz 1024
#define BD (Bsz * Dsz)
#define NBLK 128   // recurrence grid size (single wave)
#define RTHREADS 512

// ---------------- device scratch ----------------
__device__ float g_Wx[2048L * Bsz * Dsz];   // precomputed x @ W_x^T  (268 MB)
__device__ float g_scale;                   // spectral scaling of W_h
__device__ unsigned int g_arrive4[128];     // 4 barriers, 128B-padded (index ib*32)

// ---------------- scoped atomic helpers ----------------
__device__ __forceinline__ unsigned int ld_acquire_gpu(const unsigned int* p) {
    unsigned int v;
    asm volatile("ld.acquire.gpu.global.u32 %0, [%1];" : "=r"(v) : "l"(p) : "memory");
    return v;
}
__device__ __forceinline__ void red_release_gpu_add(unsigned int* p, unsigned int v) {
    asm volatile("red.release.gpu.global.add.u32 [%0], %1;" :: "l"(p), "r"(v) : "memory");
}

// ---------------- reset + h0 copy ----------------
__global__ void reset_copy_kernel(const float* __restrict__ h0, float* __restrict__ hglob) {
    int i = blockIdx.x * blockDim.x + threadIdx.x;
    if (i < 128) g_arrive4[i] = 0u;
    if (i < BD) hglob[i] = h0[i];
}

// ---------------- block reduction helper ----------------
__device__ __forceinline__ float block_reduce_sum(float v, float* red) {
    int lane = threadIdx.x & 31, w = threadIdx.x >> 5;
    #pragma unroll
    for (int o = 16; o; o >>= 1) v += __shfl_xor_sync(0xffffffffu, v, o);
    if (lane == 0) red[w] = v;
    __syncthreads();
    if (w == 0) {
        float r = (lane < (int)(blockDim.x >> 5)) ? red[lane] : 0.0f;
        #pragma unroll
        for (int o = 16; o; o >>= 1) r += __shfl_xor_sync(0xffffffffu, r, o);
        if (lane == 0) red[0] = r;
    }
    __syncthreads();
    float out = red[0];
    __syncthreads();
    return out;
}

// ---------------- spectral norm (1 CTA, 1024 threads) ----------------
__global__ __launch_bounds__(1024) void spectral_kernel(
    const float* __restrict__ W, const float* __restrict__ u0) {
    __shared__ float u_sh[Dsz];
    __shared__ float v_sh[Dsz];
    __shared__ float red[32];
    int i = threadIdx.x;

    float u0v = u0[i];
    float n0 = sqrtf(block_reduce_sum(u0v * u0v, red));
    u_sh[i] = u0v / n0;     // reference: no eps on the initial normalize
    __syncthreads();

    float sigma = 0.0f;
    for (int it = 0; it < 3; it++) {
        // v = W^T u  (column access, coalesced across threads)
        float acc = 0.0f;
        #pragma unroll 8
        for (int k = 0; k < Dsz; k++) acc += W[k * Dsz + i] * u_sh[k];
        float nv = sqrtf(block_reduce_sum(acc * acc, red));
        v_sh[i] = acc / (nv + EPS);
        __syncthreads();
        // u_raw = W v  (row access per thread)
        float acc2 = 0.0f;
        #pragma unroll 8
        for (int c = 0; c < Dsz; c++) acc2 += W[i * Dsz + c] * v_sh[c];
        float ss = block_reduce_sum(acc2 * acc2, red);
        float nu = sqrtf(ss);
        u_sh[i] = acc2 / (nu + EPS);
        __syncthreads();
        sigma = ss / (nu + EPS);
    }
    if (i == 0) g_scale = TARGET_RADIUS / (sigma + EPS);
}

// ---------------- Wx GEMM:  C[M][1024] = A[M][1024] * B[1024][1024]^T ----------------
__global__ __launch_bounds__(256) void gemm_xwx_kernel(
    const float* __restrict__ A, const float* __restrict__ B, int M) {
    __shared__ float As[16][132];
    __shared__ float Bs[16][132];
    int tid = threadIdx.x;
    int m0 = blockIdx.y * 128, n0 = blockIdx.x * 128;
    int tx = tid & 15, ty = tid >> 4;
    int lr = tid >> 2;            // 0..63
    int lc = (tid & 3) << 2;      // 0,4,8,12

    float acc[8][8];
    #pragma unroll
    for (int i = 0; i < 8; i++)
        #pragma unroll
        for (int j = 0; j < 8; j++) acc[i][j] = 0.0f;

    const float* Aptr = A + (size_t)(m0 + lr) * Dsz + lc;
    const float* Bptr = B + (size_t)(n0 + lr) * Dsz + lc;

    for (int k0 = 0; k0 < Dsz; k0 += 16) {
        float4 a0 = *(const float4*)(Aptr);
        float4 a1 = *(const float4*)(Aptr + 64 * Dsz);
        float4 b0 = *(const float4*)(Bptr);
        float4 b1 = *(const float4*)(Bptr + 64 * Dsz);
        Aptr += 16; Bptr += 16;
        __syncthreads();
        As[lc + 0][lr] = a0.x; As[lc + 1][lr] = a0.y; As[lc + 2][lr] = a0.z; As[lc + 3][lr] = a0.w;
        As[lc + 0][lr + 64] = a1.x; As[lc + 1][lr + 64] = a1.y; As[lc + 2][lr + 64] = a1.z; As[lc + 3][lr + 64] = a1.w;
        Bs[lc + 0][lr] = b0.x; Bs[lc + 1][lr] = b0.y; Bs[lc + 2][lr] = b0.z; Bs[lc + 3][lr] = b0.w;
        Bs[lc + 0][lr + 64] = b1.x; Bs[lc + 1][lr + 64] = b1.y; Bs[lc + 2][lr + 64] = b1.z; Bs[lc + 3][lr + 64] = b1.w;
        __syncthreads();
        #pragma unroll
        for (int kk = 0; kk < 16; kk++) {
            float a[8], b[8];
            *(float4*)(a)     = *(const float4*)&As[kk][ty * 4];
            *(float4*)(a + 4) = *(const float4*)&As[kk][64 + ty * 4];
            *(float4*)(b)     = *(const float4*)&Bs[kk][tx * 4];
            *(float4*)(b + 4) = *(const float4*)&Bs[kk][64 + tx * 4];
            #pragma unroll
            for (int i = 0; i < 8; i++)
                #pragma unroll
                for (int j = 0; j < 8; j++) acc[i][j] += a[i] * b[j];
        }
    }
    #pragma unroll
    for (int i = 0; i < 8; i++) {
        int m = m0 + ((i < 4) ? (ty * 4 + i) : (64 + ty * 4 + (i - 4)));
        float4 v0 = make_float4(acc[i][0], acc[i][1], acc[i][2], acc[i][3]);
        float4 v1 = make_float4(acc[i][4], acc[i][5], acc[i][6], acc[i][7]);
        *(float4*)&g_Wx[(size_t)m * Dsz + n0 + tx * 4]      = v0;
        *(float4*)&g_Wx[(size_t)m * Dsz + n0 + 64 + tx * 4] = v1;
    }
}

// ---------------- persistent recurrence kernel (128 CTAs x 512 thr, b-group barriers) ----------------
__global__ __launch_bounds__(RTHREADS, 1) void recur_kernel(
    const float* __restrict__ Wh, const float* __restrict__ bvec,
    const float* __restrict__ bgate, float* __restrict__ outp,
    float* __restrict__ hglob, int T) {
    __shared__ float4 sh_h[8 * 256];   // 8 b-rows x 256 quads, XOR-swizzled, 32 KB
    const int tid = threadIdx.x;
    const int warp = tid >> 5, lane = tid & 31;
    const int ib = blockIdx.x & 3;        // b group (4)
    const int id = blockIdx.x >> 2;       // d group (32)
    const int d_base = id * 32 + warp * 2;   // warp owns 2 d-rows
    const int b_base = ib * 8;
    unsigned int* arrive = &g_arrive4[ib * 32];

    // W_h_n rows in registers: warp owns 2 d-rows; lane owns k in [32*lane, 32*lane+32)
    float scale = g_scale;
    float wreg[2][32];
    #pragma unroll
    for (int r = 0; r < 2; r++) {
        const float* wrow = Wh + (size_t)(d_base + r) * Dsz + lane * 32;
        #pragma unroll
        for (int j = 0; j < 32; j++) wreg[r][j] = wrow[j] * scale;
    }

    // 4-stage butterfly leaves lane L with acc[bitrev4(L&15)]; lanes L and L^16 duplicate
    int idx4 = ((lane & 1) << 3) | ((lane & 2) << 1) | ((lane & 4) >> 1) | ((lane & 8) >> 3);
    int d_out = d_base + (idx4 >> 3);     // r in {0,1}
    int b_out = b_base + (idx4 & 7);      // b in 0..7
    size_t off = (size_t)b_out * Dsz + d_out;
    float bias_b = bvec[d_out];
    float bias_g = bgate[d_out];
    const bool writer = (lane < 16);

    for (int t = 0; t < T; t++) {
        // prefetch Wx (no dependency on barrier)
        float wx = __ldg(&g_Wx[(size_t)t * BD + off]);

        if (t > 0) {
            if (tid == 0) {
                unsigned int need = (unsigned int)(32 * t);
                while (ld_acquire_gpu(arrive) < need) { }
            }
            __syncthreads();
        }

        // stage h[t] slice into SMEM with swizzle; __ldcg (producers just wrote via L2)
        const float4* hsrc = (const float4*)(hglob + (size_t)t * BD + (size_t)b_base * Dsz);
        #pragma unroll
        for (int i2 = 0; i2 < 4; i2++) {
            int f = tid + RTHREADS * i2;       // quad index over 8 rows x 256 quads
            int b = f >> 8, q = f & 255;
            float4 v = __ldcg(&hsrc[f]);
            sh_h[(b << 8) + (q ^ ((q >> 3) & 7))] = v;
        }
        __syncthreads();

        float acc[16];
        #pragma unroll
        for (int a = 0; a < 16; a++) acc[a] = 0.0f;

        #pragma unroll
        for (int j8 = 0; j8 < 8; j8++) {
            int q = lane * 8 + j8;
            int qs = q ^ (lane & 7);
            // process b in two chunks of 4 to cap live registers
            #pragma unroll
            for (int c = 0; c < 2; c++) {
                float4 hq[4];
                #pragma unroll
                for (int bb = 0; bb < 4; bb++)
                    hq[bb] = sh_h[((c * 4 + bb) << 8) + qs];
                #pragma unroll
                for (int r = 0; r < 2; r++)
                    #pragma unroll
                    for (int bb = 0; bb < 4; bb++) {
                        int a = r * 8 + c * 4 + bb;
                        acc[a] += wreg[r][j8 * 4 + 0] * hq[bb].x;
                        acc[a] += wreg[r][j8 * 4 + 1] * hq[bb].y;
                        acc[a] += wreg[r][j8 * 4 + 2] * hq[bb].z;
                        acc[a] += wreg[r][j8 * 4 + 3] * hq[bb].w;
                    }
            }
        }

        // multi-value butterfly: 16 accs over bits 0..3, then full-sum across bit 4
        #pragma unroll
        for (int s = 0; s < 4; s++) {
            int bit = 1 << s, n = 8 >> s;
            #pragma unroll
            for (int j = 0; j < n; j++) {
                float send = (lane & bit) ? acc[j] : acc[j + n];
                float recv = __shfl_xor_sync(0xffffffffu, send, bit);
                acc[j] = ((lane & bit) ? acc[j + n] : acc[j]) + recv;
            }
        }
        float dot = acc[0] + __shfl_xor_sync(0xffffffffu, acc[0], 16);

        float raw = dot + wx + bias_b;
        float h_new = tanhf(raw);
        float g = wx + h_new + bias_g;
        float outv = h_new * (g / (1.0f + __expf(-g)));

        if (writer) {
            hglob[(size_t)(t + 1) * BD + off] = h_new;
            outp[(size_t)t * BD + off] = outv;
        }

        // b-group barrier arrive: cta barrier + single release-red (morally-strong pattern)
        __syncthreads();
        if (tid == 0) red_release_gpu_add(arrive, 1u);
    }
}

// ---------------- launch ----------------
extern "C" void kernel_launch(void* const* d_in, const int* in_sizes, int n_in,
                              void* d_out, int out_size) {
    const float* x   = (const float*)d_in[0];
    // d_in[1] = z (unused by reference in this gate mode)
    const float* h0  = (const float*)d_in[2];
    const float* W_x = (const float*)d_in[3];
    const float* W_h = (const float*)d_in[4];
    const float* bv  = (const float*)d_in[5];
    const float* bg  = (const float*)d_in[6];
    const float* u0  = (const float*)d_in[7];

    int T = in_sizes[0] / BD;
    float* outp  = (float*)d_out;                 // [T, B, D]
    float* hglob = outp + (size_t)T * BD;         // [T+1, B, D]

    reset_copy_kernel<<<32, 1024>>>(h0, hglob);
    spectral_kernel<<<1, 1024>>>(W_h, u0);
    dim3 grid_g(Dsz / 128, (T * Bsz) / 128);
    gemm_xwx_kernel<<<grid_g, 256>>>(x, W_x, T * Bsz);
    recur_kernel<<<NBLK, RTHREADS>>>(W_h, bv, bg, outp, hglob, T);
}

// round 5
// speedup vs baseline: 1.5100x; 1.0226x over previous
#include <cuda_runtime.h>
#include <math.h>

#define EPS 1e-8f
#define TARGET_RADIUS 0.99f
#define Bsz 32
#define Dsz 1024
#define BD (Bsz * Dsz)
#define NBLK 128   // recurrence grid size (single wave)
#define RTHREADS 512

typedef unsigned long long ull;

// ---------------- packed f32x2 helpers (sm_103a) ----------------
__device__ __forceinline__ ull f32x2_pack(float lo, float hi) {
    ull r;
    asm("mov.b64 %0, {%1, %2};" : "=l"(r) : "f"(lo), "f"(hi));
    return r;
}
__device__ __forceinline__ void f32x2_unpack(ull p, float& lo, float& hi) {
    asm("mov.b64 {%0, %1}, %2;" : "=f"(lo), "=f"(hi) : "l"(p));
}
__device__ __forceinline__ ull f32x2_fma(ull a, ull b, ull c) {
    ull d;
    asm("fma.rn.f32x2 %0, %1, %2, %3;" : "=l"(d) : "l"(a), "l"(b), "l"(c));
    return d;
}

// ---------------- device scratch ----------------
__device__ float g_Wx[2048L * Bsz * Dsz];   // precomputed x @ W_x^T  (268 MB)
__device__ float g_scale;                   // spectral scaling of W_h
__device__ unsigned int g_arrive4[128];     // 4 barriers, 128B-padded (index ib*32)

// ---------------- scoped atomic helpers ----------------
__device__ __forceinline__ unsigned int ld_acquire_gpu(const unsigned int* p) {
    unsigned int v;
    asm volatile("ld.acquire.gpu.global.u32 %0, [%1];" : "=r"(v) : "l"(p) : "memory");
    return v;
}
__device__ __forceinline__ void red_release_gpu_add(unsigned int* p, unsigned int v) {
    asm volatile("red.release.gpu.global.add.u32 [%0], %1;" :: "l"(p), "r"(v) : "memory");
}

// ---------------- reset + h0 copy ----------------
__global__ void reset_copy_kernel(const float* __restrict__ h0, float* __restrict__ hglob) {
    int i = blockIdx.x * blockDim.x + threadIdx.x;
    if (i < 128) g_arrive4[i] = 0u;
    if (i < BD) hglob[i] = h0[i];
}

// ---------------- block reduction helper ----------------
__device__ __forceinline__ float block_reduce_sum(float v, float* red) {
    int lane = threadIdx.x & 31, w = threadIdx.x >> 5;
    #pragma unroll
    for (int o = 16; o; o >>= 1) v += __shfl_xor_sync(0xffffffffu, v, o);
    if (lane == 0) red[w] = v;
    __syncthreads();
    if (w == 0) {
        float r = (lane < (int)(blockDim.x >> 5)) ? red[lane] : 0.0f;
        #pragma unroll
        for (int o = 16; o; o >>= 1) r += __shfl_xor_sync(0xffffffffu, r, o);
        if (lane == 0) red[0] = r;
    }
    __syncthreads();
    float out = red[0];
    __syncthreads();
    return out;
}

// ---------------- spectral norm (1 CTA, 1024 threads) ----------------
__global__ __launch_bounds__(1024) void spectral_kernel(
    const float* __restrict__ W, const float* __restrict__ u0) {
    __shared__ float u_sh[Dsz];
    __shared__ float v_sh[Dsz];
    __shared__ float red[32];
    int i = threadIdx.x;

    float u0v = u0[i];
    float n0 = sqrtf(block_reduce_sum(u0v * u0v, red));
    u_sh[i] = u0v / n0;     // reference: no eps on the initial normalize
    __syncthreads();

    float sigma = 0.0f;
    for (int it = 0; it < 3; it++) {
        float acc = 0.0f;
        #pragma unroll 8
        for (int k = 0; k < Dsz; k++) acc += W[k * Dsz + i] * u_sh[k];
        float nv = sqrtf(block_reduce_sum(acc * acc, red));
        v_sh[i] = acc / (nv + EPS);
        __syncthreads();
        float acc2 = 0.0f;
        #pragma unroll 8
        for (int c = 0; c < Dsz; c++) acc2 += W[i * Dsz + c] * v_sh[c];
        float ss = block_reduce_sum(acc2 * acc2, red);
        float nu = sqrtf(ss);
        u_sh[i] = acc2 / (nu + EPS);
        __syncthreads();
        sigma = ss / (nu + EPS);
    }
    if (i == 0) g_scale = TARGET_RADIUS / (sigma + EPS);
}

// ---------------- Wx GEMM:  C[M][1024] = A[M][1024] * B[1024][1024]^T ----------------
// FFMA2 version: m-paired accumulators (a pairs read directly as 64-bit LDS,
// b duplicated into both halves).
__global__ __launch_bounds__(256) void gemm_xwx_kernel(
    const float* __restrict__ A, const float* __restrict__ B, int M) {
    __shared__ float As[16][132];
    __shared__ float Bs[16][132];
    int tid = threadIdx.x;
    int m0 = blockIdx.y * 128, n0 = blockIdx.x * 128;
    int tx = tid & 15, ty = tid >> 4;
    int lr = tid >> 2;            // 0..63
    int lc = (tid & 3) << 2;      // 0,4,8,12

    ull acc2[4][8];               // pair over m: acc2[i2][j] = (acc[2i2][j], acc[2i2+1][j])
    #pragma unroll
    for (int i = 0; i < 4; i++)
        #pragma unroll
        for (int j = 0; j < 8; j++) acc2[i][j] = 0ull;

    const float* Aptr = A + (size_t)(m0 + lr) * Dsz + lc;
    const float* Bptr = B + (size_t)(n0 + lr) * Dsz + lc;

    for (int k0 = 0; k0 < Dsz; k0 += 16) {
        float4 a0 = *(const float4*)(Aptr);
        float4 a1 = *(const float4*)(Aptr + 64 * Dsz);
        float4 b0 = *(const float4*)(Bptr);
        float4 b1 = *(const float4*)(Bptr + 64 * Dsz);
        Aptr += 16; Bptr += 16;
        __syncthreads();
        As[lc + 0][lr] = a0.x; As[lc + 1][lr] = a0.y; As[lc + 2][lr] = a0.z; As[lc + 3][lr] = a0.w;
        As[lc + 0][lr + 64] = a1.x; As[lc + 1][lr + 64] = a1.y; As[lc + 2][lr + 64] = a1.z; As[lc + 3][lr + 64] = a1.w;
        Bs[lc + 0][lr] = b0.x; Bs[lc + 1][lr] = b0.y; Bs[lc + 2][lr] = b0.z; Bs[lc + 3][lr] = b0.w;
        Bs[lc + 0][lr + 64] = b1.x; Bs[lc + 1][lr + 64] = b1.y; Bs[lc + 2][lr + 64] = b1.z; Bs[lc + 3][lr + 64] = b1.w;
        __syncthreads();
        #pragma unroll
        for (int kk = 0; kk < 16; kk++) {
            // a pairs: 4 x LDS.64 (adjacent m within each half)
            ull ap[4];
            ap[0] = *(const ull*)&As[kk][ty * 4 + 0];
            ap[1] = *(const ull*)&As[kk][ty * 4 + 2];
            ap[2] = *(const ull*)&As[kk][64 + ty * 4 + 0];
            ap[3] = *(const ull*)&As[kk][64 + ty * 4 + 2];
            // b values duplicated into both halves
            float4 bv0 = *(const float4*)&Bs[kk][tx * 4];
            float4 bv1 = *(const float4*)&Bs[kk][64 + tx * 4];
            ull bd[8];
            bd[0] = f32x2_pack(bv0.x, bv0.x); bd[1] = f32x2_pack(bv0.y, bv0.y);
            bd[2] = f32x2_pack(bv0.z, bv0.z); bd[3] = f32x2_pack(bv0.w, bv0.w);
            bd[4] = f32x2_pack(bv1.x, bv1.x); bd[5] = f32x2_pack(bv1.y, bv1.y);
            bd[6] = f32x2_pack(bv1.z, bv1.z); bd[7] = f32x2_pack(bv1.w, bv1.w);
            #pragma unroll
            for (int i = 0; i < 4; i++)
                #pragma unroll
                for (int j = 0; j < 8; j++)
                    acc2[i][j] = f32x2_fma(ap[i], bd[j], acc2[i][j]);
        }
    }
    // epilogue: unpack pairs and store two m-rows per i2
    #pragma unroll
    for (int i2 = 0; i2 < 4; i2++) {
        float lo[8], hi[8];
        #pragma unroll
        for (int j = 0; j < 8; j++) f32x2_unpack(acc2[i2][j], lo[j], hi[j]);
        #pragma unroll
        for (int r = 0; r < 2; r++) {
            int i = i2 * 2 + r;
            const float* row = r ? hi : lo;
            int m = m0 + ((i < 4) ? (ty * 4 + i) : (64 + ty * 4 + (i - 4)));
            float4 v0 = make_float4(row[0], row[1], row[2], row[3]);
            float4 v1 = make_float4(row[4], row[5], row[6], row[7]);
            *(float4*)&g_Wx[(size_t)m * Dsz + n0 + tx * 4]      = v0;
            *(float4*)&g_Wx[(size_t)m * Dsz + n0 + 64 + tx * 4] = v1;
        }
    }
}

// ---------------- persistent recurrence kernel ----------------
// 128 CTAs x 512 threads. CTA covers 32 d-rows x 8 b. Warp w owns k-range
// [64w, 64w+64); lane l owns d-row l -> all lanes of a warp read the SAME
// h values (LDS broadcast, no conflicts, no replication). Cross-warp
// reduction of 16 k-partials via a small SMEM buffer.
__global__ __launch_bounds__(RTHREADS, 1) void recur_kernel(
    const float* __restrict__ Wh, const float* __restrict__ bvec,
    const float* __restrict__ bgate, float* __restrict__ outp,
    float* __restrict__ hglob, int T) {
    __shared__ float sh_h[8 * 1024];     // h slice [b][k], 32 KB
    __shared__ float red[16 * 8 * 32];   // [w][b][d-lane] partials, 16 KB
    const int tid = threadIdx.x;
    const int warp = tid >> 5, lane = tid & 31;
    const int ib = blockIdx.x & 3;        // b group (4)
    const int id = blockIdx.x >> 2;       // d group (32)
    const int b_base = ib * 8;
    const int k0 = warp * 64;
    unsigned int* arrive = &g_arrive4[ib * 32];

    // weights: lane owns d-row (id*32 + lane), k in [k0, k0+64), packed pairs
    float scale = g_scale;
    ull wp[32];
    {
        const float* wrow = Wh + (size_t)(id * 32 + lane) * Dsz + k0;
        #pragma unroll
        for (int kp = 0; kp < 32; kp++)
            wp[kp] = f32x2_pack(wrow[2 * kp] * scale, wrow[2 * kp + 1] * scale);
    }

    // epilogue role: threads 0..255 each own one (b, d) output
    int bo = tid >> 5, dl = tid & 31;            // valid when tid < 256
    size_t off = (size_t)(b_base + bo) * Dsz + (id * 32 + dl);
    float bias_b = 0.0f, bias_g = 0.0f;
    if (tid < 256) {
        bias_b = bvec[id * 32 + dl];
        bias_g = bgate[id * 32 + dl];
    }

    for (int t = 0; t < T; t++) {
        // prefetch Wx before the barrier wait
        float wx = 0.0f;
        if (tid < 256) wx = __ldg(&g_Wx[(size_t)t * BD + off]);

        if (t > 0) {
            if (tid == 0) {
                unsigned int need = (unsigned int)(32 * t);
                while (ld_acquire_gpu(arrive) < need) { }
            }
            __syncthreads();
        }

        // stage h[t] slice (plain layout; reads are warp-uniform broadcasts)
        {
            const float4* hsrc = (const float4*)(hglob + (size_t)t * BD + (size_t)b_base * Dsz);
            float4* sh4 = (float4*)sh_h;
            #pragma unroll
            for (int i2 = 0; i2 < 4; i2++) {
                int f = tid + RTHREADS * i2;
                sh4[f] = __ldcg(&hsrc[f]);
            }
        }
        __syncthreads();

        // partial dot products over this warp's 64-k range, packed pairs
        ull acc2[8];
        #pragma unroll
        for (int b = 0; b < 8; b++) acc2[b] = 0ull;
        #pragma unroll
        for (int kp = 0; kp < 32; kp++) {
            ull w2 = wp[kp];
            #pragma unroll
            for (int b = 0; b < 8; b++) {
                ull hp = *(const ull*)&sh_h[b * 1024 + k0 + 2 * kp];
                acc2[b] = f32x2_fma(w2, hp, acc2[b]);
            }
        }
        // write k-partials: red[warp][b][lane]
        #pragma unroll
        for (int b = 0; b < 8; b++) {
            float lo, hi;
            f32x2_unpack(acc2[b], lo, hi);
            red[warp * 256 + b * 32 + lane] = lo + hi;
        }
        __syncthreads();

        // reduce 16 warp-partials + epilogue (threads 0..255)
        if (tid < 256) {
            float s = 0.0f;
            #pragma unroll
            for (int w = 0; w < 16; w++) s += red[w * 256 + tid];
            float raw = s + wx + bias_b;
            float h_new = tanhf(raw);
            float g = wx + h_new + bias_g;
            float outv = h_new * (g / (1.0f + __expf(-g)));
            hglob[(size_t)(t + 1) * BD + off] = h_new;
            outp[(size_t)t * BD + off] = outv;
        }

        // b-group barrier arrive: cta barrier + single release-red
        __syncthreads();
        if (tid == 0) red_release_gpu_add(arrive, 1u);
    }
}

// ---------------- launch ----------------
extern "C" void kernel_launch(void* const* d_in, const int* in_sizes, int n_in,
                              void* d_out, int out_size) {
    const float* x   = (const float*)d_in[0];
    // d_in[1] = z (unused by reference in this gate mode)
    const float* h0  = (const float*)d_in[2];
    const float* W_x = (const float*)d_in[3];
    const float* W_h = (const float*)d_in[4];
    const float* bv  = (const float*)d_in[5];
    const float* bg  = (const float*)d_in[6];
    const float* u0  = (const float*)d_in[7];

    int T = in_sizes[0] / BD;
    float* outp  = (float*)d_out;                 // [T, B, D]
    float* hglob = outp + (size_t)T * BD;         // [T+1, B, D]

    reset_copy_kernel<<<32, 1024>>>(h0, hglob);
    spectral_kernel<<<1, 1024>>>(W_h, u0);
    dim3 grid_g(Dsz / 128, (T * Bsz) / 128);
    gemm_xwx_kernel<<<grid_g, 256>>>(x, W_x, T * Bsz);
    recur_kernel<<<NBLK, RTHREADS>>>(W_h, bv, bg, outp, hglob, T);
}